// round 15
// baseline (speedup 1.0000x reference)
#include <cuda_runtime.h>

constexpr int N     = 128;
constexpr int MAXIT = 8;
constexpr int P     = 8;      // problems per CTA (one CTA per SM, single wave)
constexpr int K     = 4;      // owned problems per thread

struct SM {
    __align__(16) float d  [P][N];
    __align__(16) float dg [P][N];
    __align__(16) float sH [P][MAXIT][N];
    __align__(16) float yH [P][MAXIT][N];
    __align__(16) float qpA[P][8 * 128];   // matvec partials [prob][r][col]
    __align__(16) float sig[P][8];
    __align__(16) float eta[P][8];
    __align__(16) float c1a[P][8];
    __align__(16) float bva[P][8];
    __align__(16) float redGd[P * 4];      // gd[p]  : 4 warps of owning half
    __align__(16) float redDq[P * 8];      // dqd[p] : all 8 warps
    __align__(16) float redU [P * 4];      // udg[p]
    __align__(16) float redE [P * 4];      // err2[p]
};

__device__ __forceinline__ float warp_sum(float v) {
    #pragma unroll
    for (int o = 16; o > 0; o >>= 1) v += __shfl_xor_sync(0xffffffffu, v, o);
    return v;
}
__device__ __forceinline__ float sum4(const float* red) {
    float4 a = *reinterpret_cast<const float4*>(red);
    return (a.x + a.y) + (a.z + a.w);
}
__device__ __forceinline__ float sum8(const float* red) {
    const float4* r4 = reinterpret_cast<const float4*>(red);
    float4 a = r4[0], b = r4[1];
    return (a.x + a.y) + (a.z + a.w) + (b.x + b.y) + (b.z + b.w);
}
__device__ __forceinline__ float combine8(const float* qpA, int i) {
    float s = 0.f;
    #pragma unroll
    for (int r = 0; r < 8; r++) s += qpA[r * 128 + i];
    return s;
}
// general-path row dot for arbitrary Hinit (not taken when Hinit == I)
__device__ __forceinline__ float rowdot(const float* __restrict__ Hrow,
                                        const float* v) {
    const float4* h4 = reinterpret_cast<const float4*>(Hrow);
    const float4* v4 = reinterpret_cast<const float4*>(v);
    float acc = 0.f;
    #pragma unroll 8
    for (int k = 0; k < 32; k++) {
        float4 hh = h4[k], vv = v4[k];
        acc += hh.x * vv.x + hh.y * vv.y + hh.z * vv.z + hh.w * vv.w;
    }
    return acc;
}

__global__ __launch_bounds__(256, 1)
void bfgs_kernel(const float* __restrict__ Hinit,
                 const float* __restrict__ Q,
                 const float* __restrict__ bvec,
                 const float* __restrict__ x0,
                 float* __restrict__ out)
{
    extern __shared__ char smraw[];
    SM& sm = *reinterpret_cast<SM*>(smraw);

    const int t     = threadIdx.x;
    const int i     = t & 127;         // owned element
    const int half  = t >> 7;          // owner probs: 4*half .. 4*half+3
    const int c     = t & 31;          // matvec: column group (4c..4c+3)
    const int r     = t >> 5;          // matvec: k-range / history slot (warp id)
    const int rr    = r & 3;           // warp index within its half
    const int pbase = half * 4;
    const int gbase = P * blockIdx.x;

    // ---- stage x0 for owned problems; identity check on Hinit (L2-shared);
    //      __syncthreads_and doubles as the staging barrier ----
    float x[K], g[K], d[K];
    #pragma unroll
    for (int k = 0; k < K; k++) {
        x[k] = x0[(gbase + pbase + k) * N + i];
        sm.d[pbase + k][i] = x[k];
    }
    int ok = 1;
    {
        const float4* H4 = reinterpret_cast<const float4*>(Hinit);
        #pragma unroll 4
        for (int idx = t; idx < 4096; idx += 256) {
            const int base = idx * 4;
            const int row  = base >> 7;
            const int col  = base & 127;
            float4 v = H4[idx];
            ok &= (v.x == ((row == col + 0) ? 1.f : 0.f));
            ok &= (v.y == ((row == col + 1) ? 1.f : 0.f));
            ok &= (v.z == ((row == col + 2) ? 1.f : 0.f));
            ok &= (v.w == ((row == col + 3) ? 1.f : 0.f));
        }
    }
    const int identity = __syncthreads_and(ok);

    // ---- matvec: 16 LDG.128 cover Q once; partials for all 8 problems ----
    auto qmv = [&](float4* A) {
        #pragma unroll
        for (int p = 0; p < P; p++) A[p] = make_float4(0.f, 0.f, 0.f, 0.f);
        const float4* qr4 = reinterpret_cast<const float4*>(Q + (size_t)(16 * r) * N) + c;
        #pragma unroll 1
        for (int jj = 0; jj < 4; jj++) {
            float4 q0 = qr4[(4 * jj + 0) * 32];
            float4 q1 = qr4[(4 * jj + 1) * 32];
            float4 q2 = qr4[(4 * jj + 2) * 32];
            float4 q3 = qr4[(4 * jj + 3) * 32];
            #pragma unroll
            for (int p = 0; p < P; p++) {
                float4 u = reinterpret_cast<const float4*>(sm.d[p] + 16 * r)[jj];
                A[p].x += q0.x*u.x + q1.x*u.y + q2.x*u.z + q3.x*u.w;
                A[p].y += q0.y*u.x + q1.y*u.y + q2.y*u.z + q3.y*u.w;
                A[p].z += q0.z*u.x + q1.z*u.y + q2.z*u.z + q3.z*u.w;
                A[p].w += q0.w*u.x + q1.w*u.y + q2.w*u.z + q3.w*u.w;
            }
        }
        #pragma unroll
        for (int p = 0; p < P; p++)
            reinterpret_cast<float4*>(sm.qpA[p])[t] = A[p];
    };

    // ---- g0 = Q x0 - b ----
    {
        float4 A[P];
        qmv(A);
    }
    __syncthreads();
    #pragma unroll
    for (int k = 0; k < K; k++)
        g[k] = combine8(sm.qpA[pbase + k], i) - bvec[(gbase + pbase + k) * N + i];

    // ---- d0 = -H0 g0 ----
    if (identity) {
        #pragma unroll
        for (int k = 0; k < K; k++) { d[k] = -g[k]; sm.d[pbase + k][i] = d[k]; }
        __syncthreads();
    } else {
        #pragma unroll
        for (int k = 0; k < K; k++) sm.dg[pbase + k][i] = g[k];
        __syncthreads();
        #pragma unroll
        for (int k = 0; k < K; k++) {
            d[k] = -rowdot(Hinit + (size_t)i * N, sm.dg[pbase + k]);
            sm.d[pbase + k][i] = d[k];
        }
        __syncthreads();
    }

    bool m[K];
    #pragma unroll
    for (int k = 0; k < K; k++) m[k] = true;

    #pragma unroll 1
    for (int it = 0; it < MAXIT; ++it) {
        // ===== Phase A: qd = Q d (8 problems); gd, dQd =====
        float4 A[P];
        qmv(A);
        #pragma unroll
        for (int p = 0; p < P; p++) {
            float4 u = reinterpret_cast<const float4*>(sm.d[p])[c];
            float dq = A[p].x*u.x + A[p].y*u.y + A[p].z*u.z + A[p].w*u.w;
            dq = warp_sum(dq);
            if (c == 0) sm.redDq[p * 8 + r] = dq;
        }
        #pragma unroll
        for (int k = 0; k < K; k++) {
            float gd = warp_sum(g[k] * d[k]);     // warp is half-uniform
            if (c == 0) sm.redGd[(pbase + k) * 4 + rr] = gd;
        }
        __syncthreads();                                   // S1

        float al[K], sdg[K], gd_[K], dqd_[K], dg_[K], s_[K];
        #pragma unroll
        for (int k = 0; k < K; k++) {
            const int p = pbase + k;
            gd_[k]  = sum4(sm.redGd + p * 4);
            dqd_[k] = sum8(sm.redDq + p * 8);
            al[k]   = -gd_[k] / fmaxf(dqd_[k], 1e-12f);
            sdg[k]  = al[k] * al[k] * dqd_[k];             // s.dg exactly
            dg_[k]  = al[k] * combine8(sm.qpA[p], i);      // dg = a*Qd
            s_[k]   = al[k] * d[k];
            sm.dg[p][i]     = dg_[k];
            sm.sH[p][it][i] = s_[k];
        }
        __syncthreads();                                   // S2

        // ===== history dots: warp r handles slot j = r for all 8 problems =====
        if (r < it) {
            #pragma unroll
            for (int p = 0; p < P; p++) {
                float4 dv = reinterpret_cast<const float4*>(sm.dg[p])[c];
                float4 sv = reinterpret_cast<const float4*>(sm.sH[p][r])[c];
                float4 yv = reinterpret_cast<const float4*>(sm.yH[p][r])[c];
                float sp = warp_sum(sv.x*dv.x + sv.y*dv.y + sv.z*dv.z + sv.w*dv.w);
                float ep = warp_sum(yv.x*dv.x + yv.y*dv.y + yv.z*dv.z + yv.w*dv.w);
                if (c == 0) { sm.sig[p][r] = sp; sm.eta[p][r] = ep; }
            }
        }
        // base u = H0*dg; commit x,g with OLD mask; owner reductions udg, err2
        float u_[K];
        #pragma unroll
        for (int k = 0; k < K; k++) u_[k] = dg_[k];
        if (!identity) {
            #pragma unroll
            for (int k = 0; k < K; k++)
                u_[k] = rowdot(Hinit + (size_t)i * N, sm.dg[pbase + k]);
        }
        #pragma unroll
        for (int k = 0; k < K; k++) {
            const float gc = m[k] ? g[k] + dg_[k] : g[k];
            x[k] = m[k] ? x[k] + s_[k] : x[k];
            g[k] = gc;
            float uA = warp_sum(dg_[k] * u_[k]);
            float eA = warp_sum(gc * gc);
            if (c == 0) {
                sm.redU[(pbase + k) * 4 + rr] = uA;
                sm.redE[(pbase + k) * 4 + rr] = eA;
            }
        }
        __syncthreads();                                   // S3

        // ===== hy (low-rank) + scalar ihdg; coeffs; d recurrence =====
        #pragma unroll
        for (int k = 0; k < K; k++) {
            const int p = pbase + k;
            const float udg = sum4(sm.redU + p * 4);
            const float e2  = sum4(sm.redE + p * 4);
            float hy = u_[k], ih = udg;
            #pragma unroll
            for (int j = 0; j < MAXIT; ++j) {
                if (j < it) {
                    const float c1j = sm.c1a[p][j], bj = sm.bva[p][j];
                    const float sg  = sm.sig[p][j], et = sm.eta[p][j];
                    const float wj  = c1j * sg - bj * et;
                    const float vj  = -bj * sg;
                    hy += wj * sm.sH[p][j][i] + vj * sm.yH[p][j][i];
                    ih += sg * wj + et * vj;
                }
            }
            const float biv = (sdg[k] != 0.f) ? 1.f / sdg[k] : 0.f;
            const float c1  = (sdg[k] != 0.f) ? (sdg[k] + ih) * biv * biv : 0.f;
            const float mf   = m[k] ? 1.f : 0.f;
            const float sgn  = al[k] * gd_[k] + mf * sdg[k];   // s . g_committed
            const float hygn = mf * ih - al[k] * dqd_[k];      // Hy . g_committed
            const float cs   = biv * hygn - c1 * sgn;
            const float ch   = biv * sgn - mf;
            d[k] = d[k] + cs * s_[k] + ch * hy;                // == -H_new g_new
            sm.d[p][i]      = d[k];
            sm.yH[p][it][i] = hy;
            if (i == 0) { sm.c1a[p][it] = c1; sm.bva[p][it] = biv; }
            m[k] = m[k] && (e2 > 1e-12f);   // err > 1e-6  <=>  err^2 > 1e-12
        }
        __syncthreads();                                   // S4
    }

    #pragma unroll
    for (int k = 0; k < K; k++)
        out[(gbase + pbase + k) * N + i] = x[k];
}

extern "C" void kernel_launch(void* const* d_in, const int* in_sizes, int n_in,
                              void* d_out, int out_size)
{
    const float* Hinit = (const float*)d_in[0];
    const float* Q     = (const float*)d_in[1];
    const float* bvec  = (const float*)d_in[2];
    const float* x0    = (const float*)d_in[3];
    float*       out   = (float*)d_out;

    const int nprob = out_size / N;    // B*E = 1024 (divisible by 8)
    const int smem  = (int)sizeof(SM);

    cudaFuncSetAttribute(bfgs_kernel, cudaFuncAttributeMaxDynamicSharedMemorySize, smem);
    bfgs_kernel<<<nprob / P, 256, smem>>>(Hinit, Q, bvec, x0, out);
}

// round 16
// speedup vs baseline: 1.6787x; 1.6787x over previous
#include <cuda_runtime.h>

constexpr int N     = 128;
constexpr int MAXIT = 8;
constexpr int P     = 4;      // problems per CTA
constexpr int K     = 2;      // owned problems per thread

__device__ int g_hid;         // 1 if Hinit == identity

__global__ void check_hinit_kernel(const float4* __restrict__ H4) {
    int ok = 1;
    for (int idx = threadIdx.x; idx < 4096; idx += blockDim.x) {
        const int base = idx * 4;
        const int row  = base >> 7;
        const int col  = base & 127;
        float4 v = H4[idx];
        ok &= (v.x == ((row == col + 0) ? 1.f : 0.f));
        ok &= (v.y == ((row == col + 1) ? 1.f : 0.f));
        ok &= (v.z == ((row == col + 2) ? 1.f : 0.f));
        ok &= (v.w == ((row == col + 3) ? 1.f : 0.f));
    }
    ok = __syncthreads_and(ok);
    if (threadIdx.x == 0) g_hid = ok;
}

struct SM {
    __align__(16) float d   [P][N];
    __align__(16) float vbuf[P][N];       // general-H0 path staging only
    __align__(16) float qpA [P][8 * 128]; // matvec partials [prob][r][col]
    __align__(16) float redGd[P * 4];     // g.d   : 4 warps of owning half
    __align__(16) float redDq[P * 8];     // d.Qd  : all 8 warps
    __align__(16) float redZ [P * 4];     // gn.zn
    __align__(16) float redE [P * 4];     // gn.gn (general path)
};

__device__ __forceinline__ float warp_sum(float v) {
    #pragma unroll
    for (int o = 16; o > 0; o >>= 1) v += __shfl_xor_sync(0xffffffffu, v, o);
    return v;
}
__device__ __forceinline__ float sum4(const float* red) {
    float4 a = *reinterpret_cast<const float4*>(red);
    return (a.x + a.y) + (a.z + a.w);
}
__device__ __forceinline__ float sum8(const float* red) {
    const float4* r4 = reinterpret_cast<const float4*>(red);
    float4 a = r4[0], b = r4[1];
    return (a.x + a.y) + (a.z + a.w) + (b.x + b.y) + (b.z + b.w);
}
__device__ __forceinline__ float combine8(const float* qpA, int i) {
    float s = 0.f;
    #pragma unroll
    for (int r = 0; r < 8; r++) s += qpA[r * 128 + i];
    return s;
}
// general-path row dot for arbitrary (SPD) Hinit — not taken when Hinit == I
__device__ __forceinline__ float rowdot(const float* __restrict__ Hrow,
                                        const float* v) {
    const float4* h4 = reinterpret_cast<const float4*>(Hrow);
    const float4* v4 = reinterpret_cast<const float4*>(v);
    float acc = 0.f;
    #pragma unroll 8
    for (int k = 0; k < 32; k++) {
        float4 hh = h4[k], vv = v4[k];
        acc += hh.x * vv.x + hh.y * vv.y + hh.z * vv.z + hh.w * vv.w;
    }
    return acc;
}

__global__ __launch_bounds__(256, 4)
void bfgs_kernel(const float* __restrict__ Hinit,
                 const float* __restrict__ Q,
                 const float* __restrict__ bvec,
                 const float* __restrict__ x0,
                 float* __restrict__ out)
{
    extern __shared__ char smraw[];
    SM& sm = *reinterpret_cast<SM*>(smraw);

    const int t    = threadIdx.x;
    const int i    = t & 127;          // owned element
    const int half = t >> 7;           // owner probs: half, half+2
    const int c    = t & 31;           // matvec: column group (4c..4c+3)
    const int r    = t >> 5;           // matvec: k-range (warp id)
    const int rr   = r & 3;            // warp index within its half
    const int pa   = half, pb = half + 2;
    const int gpa  = P * blockIdx.x + pa;
    const int gpb  = P * blockIdx.x + pb;

    const int identity = g_hid;        // block-uniform

    // ---- stage x0 ----
    float xa = x0[gpa * N + i], xb = x0[gpb * N + i];
    sm.d[pa][i] = xa;  sm.d[pb][i] = xb;
    __syncthreads();

    // ---- matvec: partials for all 4 problems sharing each Q load ----
    auto qmv4 = [&](float4& A0, float4& A1, float4& A2, float4& A3) {
        const float4* qr4 = reinterpret_cast<const float4*>(Q + (size_t)(16 * r) * N) + c;
        const float4* k0 = reinterpret_cast<const float4*>(sm.d[0] + 16 * r);
        const float4* k1 = reinterpret_cast<const float4*>(sm.d[1] + 16 * r);
        const float4* k2 = reinterpret_cast<const float4*>(sm.d[2] + 16 * r);
        const float4* k3 = reinterpret_cast<const float4*>(sm.d[3] + 16 * r);
        A0 = make_float4(0.f, 0.f, 0.f, 0.f); A1 = A0; A2 = A0; A3 = A0;
        #pragma unroll 1
        for (int jj = 0; jj < 4; jj++) {
            float4 q0 = qr4[(4 * jj + 0) * 32];
            float4 q1 = qr4[(4 * jj + 1) * 32];
            float4 q2 = qr4[(4 * jj + 2) * 32];
            float4 q3 = qr4[(4 * jj + 3) * 32];
            float4 u;
            u = k0[jj];
            A0.x += q0.x*u.x + q1.x*u.y + q2.x*u.z + q3.x*u.w;
            A0.y += q0.y*u.x + q1.y*u.y + q2.y*u.z + q3.y*u.w;
            A0.z += q0.z*u.x + q1.z*u.y + q2.z*u.z + q3.z*u.w;
            A0.w += q0.w*u.x + q1.w*u.y + q2.w*u.z + q3.w*u.w;
            u = k1[jj];
            A1.x += q0.x*u.x + q1.x*u.y + q2.x*u.z + q3.x*u.w;
            A1.y += q0.y*u.x + q1.y*u.y + q2.y*u.z + q3.y*u.w;
            A1.z += q0.z*u.x + q1.z*u.y + q2.z*u.z + q3.z*u.w;
            A1.w += q0.w*u.x + q1.w*u.y + q2.w*u.z + q3.w*u.w;
            u = k2[jj];
            A2.x += q0.x*u.x + q1.x*u.y + q2.x*u.z + q3.x*u.w;
            A2.y += q0.y*u.x + q1.y*u.y + q2.y*u.z + q3.y*u.w;
            A2.z += q0.z*u.x + q1.z*u.y + q2.z*u.z + q3.z*u.w;
            A2.w += q0.w*u.x + q1.w*u.y + q2.w*u.z + q3.w*u.w;
            u = k3[jj];
            A3.x += q0.x*u.x + q1.x*u.y + q2.x*u.z + q3.x*u.w;
            A3.y += q0.y*u.x + q1.y*u.y + q2.y*u.z + q3.y*u.w;
            A3.z += q0.z*u.x + q1.z*u.y + q2.z*u.z + q3.z*u.w;
            A3.w += q0.w*u.x + q1.w*u.y + q2.w*u.z + q3.w*u.w;
        }
        reinterpret_cast<float4*>(sm.qpA[0])[t] = A0;
        reinterpret_cast<float4*>(sm.qpA[1])[t] = A1;
        reinterpret_cast<float4*>(sm.qpA[2])[t] = A2;
        reinterpret_cast<float4*>(sm.qpA[3])[t] = A3;
    };

    // ---- g0 = Q x0 - b ----
    {
        float4 A0, A1, A2, A3;
        qmv4(A0, A1, A2, A3);
    }
    __syncthreads();
    float ga = combine8(sm.qpA[pa], i) - bvec[gpa * N + i];
    float gb = combine8(sm.qpA[pb], i) - bvec[gpb * N + i];

    // ---- z0 = H0 g0 ; d0 = -z0 ; gz0 = g0.z0 ----
    float za, zb;
    if (identity) {
        za = ga; zb = gb;
    } else {
        sm.vbuf[pa][i] = ga; sm.vbuf[pb][i] = gb;
        __syncthreads();
        za = rowdot(Hinit + (size_t)i * N, sm.vbuf[pa]);
        zb = rowdot(Hinit + (size_t)i * N, sm.vbuf[pb]);
    }
    float da = -za, db = -zb;
    sm.d[pa][i] = da; sm.d[pb][i] = db;
    {
        float wA = warp_sum(ga * za);
        float wB = warp_sum(gb * zb);
        if (c == 0) { sm.redZ[pa * 4 + rr] = wA; sm.redZ[pb * 4 + rr] = wB; }
    }
    __syncthreads();
    float gza = sum4(sm.redZ + pa * 4);
    float gzb = sum4(sm.redZ + pb * 4);

    bool ma = true, mb = true;    // per-owner-problem "updating" flags

    #pragma unroll 1
    for (int it = 0; it < MAXIT; ++it) {
        // ===== Phase A: qd = Q d (4 problems); reduce g.d, d.Qd =====
        float4 A0, A1, A2, A3;
        qmv4(A0, A1, A2, A3);
        {
            float4 u0 = reinterpret_cast<const float4*>(sm.d[0])[c];
            float4 u1 = reinterpret_cast<const float4*>(sm.d[1])[c];
            float4 u2 = reinterpret_cast<const float4*>(sm.d[2])[c];
            float4 u3 = reinterpret_cast<const float4*>(sm.d[3])[c];
            float dq0 = warp_sum(A0.x*u0.x + A0.y*u0.y + A0.z*u0.z + A0.w*u0.w);
            float dq1 = warp_sum(A1.x*u1.x + A1.y*u1.y + A1.z*u1.z + A1.w*u1.w);
            float dq2 = warp_sum(A2.x*u2.x + A2.y*u2.y + A2.z*u2.z + A2.w*u2.w);
            float dq3 = warp_sum(A3.x*u3.x + A3.y*u3.y + A3.z*u3.z + A3.w*u3.w);
            float gdA = warp_sum(ga * da);          // warp is half-uniform
            float gdB = warp_sum(gb * db);
            if (c == 0) {
                sm.redDq[0 * 8 + r] = dq0; sm.redDq[1 * 8 + r] = dq1;
                sm.redDq[2 * 8 + r] = dq2; sm.redDq[3 * 8 + r] = dq3;
                sm.redGd[pa * 4 + rr] = gdA;
                sm.redGd[pb * 4 + rr] = gdB;
            }
        }
        __syncthreads();                                   // S1
        const float gd_a  = sum4(sm.redGd + pa * 4);
        const float gd_b  = sum4(sm.redGd + pb * 4);
        const float dqd_a = sum8(sm.redDq + pa * 8);
        const float dqd_b = sum8(sm.redDq + pb * 8);

        const float al_a = -gd_a / fmaxf(dqd_a, 1e-12f);   // exact line search
        const float al_b = -gd_b / fmaxf(dqd_b, 1e-12f);

        // step, gradient update, commit with OLD mask
        const float gn_a = ga + al_a * combine8(sm.qpA[pa], i);
        const float gn_b = gb + al_b * combine8(sm.qpA[pb], i);
        xa = ma ? xa + al_a * da : xa;
        xb = mb ? xb + al_b * db : xb;

        // z_new = H0 g_new
        float zn_a, zn_b;
        float e2wA = 0.f, e2wB = 0.f;
        if (identity) {
            zn_a = gn_a; zn_b = gn_b;
        } else {
            sm.vbuf[pa][i] = gn_a; sm.vbuf[pb][i] = gn_b;
            __syncthreads();                               // (general path only)
            zn_a = rowdot(Hinit + (size_t)i * N, sm.vbuf[pa]);
            zn_b = rowdot(Hinit + (size_t)i * N, sm.vbuf[pb]);
            e2wA = warp_sum(gn_a * gn_a);
            e2wB = warp_sum(gn_b * gn_b);
        }
        {
            float wA = warp_sum(gn_a * zn_a);              // gn.zn (identity: = |gn|^2)
            float wB = warp_sum(gn_b * zn_b);
            if (c == 0) {
                sm.redZ[pa * 4 + rr] = wA;  sm.redZ[pb * 4 + rr] = wB;
                if (!identity) { sm.redE[pa * 4 + rr] = e2wA; sm.redE[pb * 4 + rr] = e2wB; }
            }
        }
        __syncthreads();                                   // S2
        const float ngz_a = sum4(sm.redZ + pa * 4);
        const float ngz_b = sum4(sm.redZ + pb * 4);
        const float e2_a  = identity ? ngz_a : sum4(sm.redE + pa * 4);
        const float e2_b  = identity ? ngz_b : sum4(sm.redE + pb * 4);

        // CG direction update: d = -z_new + beta d
        const float be_a = ngz_a / fmaxf(gza, 1e-30f);
        const float be_b = ngz_b / fmaxf(gzb, 1e-30f);
        da = -zn_a + be_a * da;
        db = -zn_b + be_b * db;
        sm.d[pa][i] = da;  sm.d[pb][i] = db;
        ga = gn_a; gb = gn_b;
        za = zn_a; zb = zn_b;
        gza = ngz_a; gzb = ngz_b;
        ma = ma && (e2_a > 1e-12f);   // err > 1e-6  <=>  err^2 > 1e-12
        mb = mb && (e2_b > 1e-12f);
        __syncthreads();                                   // S3
    }

    out[gpa * N + i] = xa;
    out[gpb * N + i] = xb;
}

extern "C" void kernel_launch(void* const* d_in, const int* in_sizes, int n_in,
                              void* d_out, int out_size)
{
    const float* Hinit = (const float*)d_in[0];
    const float* Q     = (const float*)d_in[1];
    const float* bvec  = (const float*)d_in[2];
    const float* x0    = (const float*)d_in[3];
    float*       out   = (float*)d_out;

    const int nprob = out_size / N;    // B*E = 1024 (divisible by 4)
    const int smem  = (int)sizeof(SM);

    cudaFuncSetAttribute(bfgs_kernel, cudaFuncAttributeMaxDynamicSharedMemorySize, smem);
    check_hinit_kernel<<<1, 1024>>>(reinterpret_cast<const float4*>(Hinit));
    bfgs_kernel<<<nprob / P, 256, smem>>>(Hinit, Q, bvec, x0, out);
}